// round 1
// baseline (speedup 1.0000x reference)
#include <cuda_runtime.h>
#include <math.h>

// Problem constants
constexpr int cN   = 4;
constexpr int cH   = 128;
constexpr int cW   = 256;
constexpr int CIN1 = 96,  COUT1 = 128;
constexpr int CIN2 = 128, COUT2 = 144;
constexpr int HW   = cH * cW;

// Scratch (static device allocation — no cudaMalloc allowed)
__device__ float g_hfeat[cN * COUT1 * cH * cW];   // 67 MB
__device__ float g_mask [cN * COUT2 * cH * cW];   // 75 MB

// ---------------------------------------------------------------------------
// 3x3 SAME conv, NCHW, register-blocked implicit GEMM.
// Tile: NT=64 pixels (one row segment) x MT output channels.
// 256 threads = 16 (pixel groups) x 16 (channel groups); micro-tile MR x 4.
// K-chunks of KC=8 input channels (72 k-steps per chunk).
// ---------------------------------------------------------------------------
template<int CIN, int COUT, int MT, bool LRELU>
__global__ __launch_bounds__(256, 2)
void conv3x3_kernel(const float* __restrict__ in,
                    const float* __restrict__ wt,
                    const float* __restrict__ bias,
                    float* __restrict__ out)
{
    constexpr int NT = 64;
    constexpr int KC = 8;
    constexpr int KSTEP = KC * 9;        // 72
    constexpr int MR = MT / 16;          // 4 (MT=64) or 3 (MT=48)
    constexpr int IPAD = NT + 4;         // 68: keeps rows 16B-aligned
    constexpr int WPAD = (MT + 4) & ~3;  // 16B-aligned rows

    __shared__ __align__(16) float s_in[KC][3][IPAD];
    __shared__ __align__(16) float s_w[KSTEP][WPAD];

    const int tid = threadIdx.x;
    const int tx  = tid & 15;    // pixel group: pixels tx*4 .. tx*4+3
    const int ty  = tid >> 4;    // channel group: channels ty*MR .. +MR-1

    const int x0 = blockIdx.x * NT;
    const int y  = blockIdx.y;
    constexpr int MTILES = COUT / MT;
    const int n   = blockIdx.z / MTILES;
    const int co0 = (blockIdx.z % MTILES) * MT;

    float acc[MR][4];
    #pragma unroll
    for (int i = 0; i < MR; i++)
        #pragma unroll
        for (int j = 0; j < 4; j++) acc[i][j] = 0.0f;

    for (int ci0 = 0; ci0 < CIN; ci0 += KC) {
        __syncthreads();  // protect previous chunk's smem reads

        // --- stage input tile: KC channels x 3 rows x 66 cols (halo) ---
        constexpr int IN_ELEMS = KC * 3 * (NT + 2);
        for (int idx = tid; idx < IN_ELEMS; idx += 256) {
            int ci  = idx / (3 * (NT + 2));
            int rem = idx % (3 * (NT + 2));
            int ky  = rem / (NT + 2);
            int xx  = rem % (NT + 2);
            int gy = y + ky - 1;
            int gx = x0 + xx - 1;
            float v = 0.0f;
            if ((unsigned)gy < (unsigned)cH && (unsigned)gx < (unsigned)cW)
                v = in[((n * CIN + ci0 + ci) * cH + gy) * cW + gx];
            s_in[ci][ky][xx] = v;
        }

        // --- stage weights k-major: s_w[k][co_l]; per-co 72 floats are
        //     contiguous in global (OIHW, ci-chunk contiguous) ---
        constexpr int W_ELEMS = MT * KSTEP;
        for (int idx = tid; idx < W_ELEMS; idx += 256) {
            int co_l = idx / KSTEP;
            int kk   = idx % KSTEP;
            s_w[kk][co_l] = wt[((co0 + co_l) * CIN + ci0) * 9 + kk];
        }
        __syncthreads();

        // --- compute: 72 k-steps, sliding 6-wide input window per (ci,ky) ---
        #pragma unroll
        for (int ci = 0; ci < KC; ci++) {
            #pragma unroll
            for (int ky = 0; ky < 3; ky++) {
                const float* bp = &s_in[ci][ky][tx * 4];
                float4 blo = *reinterpret_cast<const float4*>(bp);
                float2 bhi = *reinterpret_cast<const float2*>(bp + 4);
                float b[6] = {blo.x, blo.y, blo.z, blo.w, bhi.x, bhi.y};
                #pragma unroll
                for (int kx = 0; kx < 3; kx++) {
                    const int k = ci * 9 + ky * 3 + kx;
                    const float* ap = &s_w[k][ty * MR];
                    #pragma unroll
                    for (int i = 0; i < MR; i++) {
                        float a = ap[i];
                        #pragma unroll
                        for (int j = 0; j < 4; j++)
                            acc[i][j] = fmaf(a, b[kx + j], acc[i][j]);
                    }
                }
            }
        }
    }

    // --- epilogue: bias (+ LeakyReLU), vector store ---
    #pragma unroll
    for (int i = 0; i < MR; i++) {
        const int co = co0 + ty * MR + i;
        const float bs = __ldg(&bias[co]);
        float4 v;
        v.x = acc[i][0] + bs; v.y = acc[i][1] + bs;
        v.z = acc[i][2] + bs; v.w = acc[i][3] + bs;
        if (LRELU) {
            v.x = v.x > 0.f ? v.x : 0.1f * v.x;
            v.y = v.y > 0.f ? v.y : 0.1f * v.y;
            v.z = v.z > 0.f ? v.z : 0.1f * v.z;
            v.w = v.w > 0.f ? v.w : 0.1f * v.w;
        }
        *reinterpret_cast<float4*>(&out[((n * COUT + co) * cH + y) * cW + x0 + tx * 4]) = v;
    }
}

// ---------------------------------------------------------------------------
// Softmax over 9 kernel positions + convex combination + 4x pixel shuffle.
// One thread per (n, y, x). mask channel layout: k*16 + a*4 + b.
// ---------------------------------------------------------------------------
__global__ __launch_bounds__(256)
void upsample_kernel(const float* __restrict__ flow,
                     const float* __restrict__ mask,
                     float* __restrict__ out)
{
    const int idx = blockIdx.x * blockDim.x + threadIdx.x;
    if (idx >= cN * HW) return;
    const int x = idx % cW;
    const int y = (idx / cW) % cH;
    const int n = idx / HW;

    // 9 shifted copies of 4*flow (zero-padded), both channels
    float fpx[9], fpy[9];
    #pragma unroll
    for (int ki = 0; ki < 3; ki++)
        #pragma unroll
        for (int kj = 0; kj < 3; kj++) {
            const int k = ki * 3 + kj;
            const int yy = y + ki - 1, xx = x + kj - 1;
            const bool ok = (unsigned)yy < (unsigned)cH && (unsigned)xx < (unsigned)cW;
            fpx[k] = ok ? 4.0f * flow[(n * 2 + 0) * HW + yy * cW + xx] : 0.0f;
            fpy[k] = ok ? 4.0f * flow[(n * 2 + 1) * HW + yy * cW + xx] : 0.0f;
        }

    const long base = (long)n * COUT2 * HW + y * cW + x;
    const int OH = 4 * cH, OW = 4 * cW;

    #pragma unroll
    for (int a = 0; a < 4; a++) {
        #pragma unroll
        for (int b = 0; b < 4; b++) {
            float m[9];
            float mx = -1e30f;
            #pragma unroll
            for (int k = 0; k < 9; k++) {
                m[k] = 0.25f * mask[base + (long)(k * 16 + a * 4 + b) * HW];
                mx = fmaxf(mx, m[k]);
            }
            float s = 0.0f;
            #pragma unroll
            for (int k = 0; k < 9; k++) { m[k] = __expf(m[k] - mx); s += m[k]; }
            const float inv = 1.0f / s;
            float ox = 0.0f, oy = 0.0f;
            #pragma unroll
            for (int k = 0; k < 9; k++) { ox += m[k] * fpx[k]; oy += m[k] * fpy[k]; }
            const int oyi = y * 4 + a, oxi = x * 4 + b;
            out[((n * 2 + 0) * OH + oyi) * OW + oxi] = ox * inv;
            out[((n * 2 + 1) * OH + oyi) * OW + oxi] = oy * inv;
        }
    }
}

// ---------------------------------------------------------------------------
extern "C" void kernel_launch(void* const* d_in, const int* in_sizes, int n_in,
                              void* d_out, int out_size)
{
    (void)in_sizes; (void)n_in; (void)out_size;
    const float* flow = (const float*)d_in[0];
    const float* feat = (const float*)d_in[1];
    const float* w1   = (const float*)d_in[2];
    const float* b1   = (const float*)d_in[3];
    const float* w2   = (const float*)d_in[4];
    const float* b2   = (const float*)d_in[5];
    float* out = (float*)d_out;

    float* hfeat; float* msk;
    cudaGetSymbolAddress((void**)&hfeat, g_hfeat);
    cudaGetSymbolAddress((void**)&msk, g_mask);

    // conv1: 96 -> 128, LeakyReLU(0.1). MT=64 -> 2 exact channel tiles.
    {
        dim3 grid(cW / 64, cH, cN * (COUT1 / 64));
        conv3x3_kernel<CIN1, COUT1, 64, true><<<grid, 256>>>(feat, w1, b1, hfeat);
    }
    // conv2: 128 -> 144 (raw; 0.25 folded into softmax). MT=48 -> 3 exact tiles.
    {
        dim3 grid(cW / 64, cH, cN * (COUT2 / 48));
        conv3x3_kernel<CIN2, COUT2, 48, false><<<grid, 256>>>(hfeat, w2, b2, msk);
    }
    // softmax + convex upsample + pixel shuffle
    {
        const int total = cN * HW;
        upsample_kernel<<<(total + 255) / 256, 256>>>(flow, msk, out);
    }
}

// round 2
// speedup vs baseline: 1.2333x; 1.2333x over previous
#include <cuda_runtime.h>
#include <math.h>

// Problem constants
constexpr int cN   = 4;
constexpr int cH   = 128;
constexpr int cW   = 256;
constexpr int CIN1 = 96,  COUT1 = 128;
constexpr int CIN2 = 128, COUT2 = 144;
constexpr int HW   = cH * cW;

// Scratch (static device allocation — no cudaMalloc allowed)
__device__ float g_hfeat[cN * COUT1 * cH * cW];
__device__ float g_mask [cN * COUT2 * cH * cW];

// ---- packed f32x2 helpers ----------------------------------------------
using ull = unsigned long long;

__device__ __forceinline__ ull pk_dup(float x) {
    ull r;
    asm("mov.b64 %0, {%1, %1};" : "=l"(r) : "f"(x));
    return r;
}
__device__ __forceinline__ void fma2(ull& d, ull a, ull b) {
    asm("fma.rn.f32x2 %0, %1, %2, %0;" : "+l"(d) : "l"(a), "l"(b));
}
__device__ __forceinline__ void unpk(float& lo, float& hi, ull v) {
    asm("mov.b64 {%0, %1}, %2;" : "=f"(lo), "=f"(hi) : "l"(v));
}

// ---------------------------------------------------------------------------
// 3x3 SAME conv, NCHW, register-blocked implicit GEMM with packed f32x2 FMA.
// Tile: NT=128 pixels (half a row) x MT output channels.
// 256 threads = 32 (pixel groups, 4 px each) x 8 (channel groups, MR ch each).
// Packing is over the CHANNEL dim: weight pairs load straight from smem as
// 8-byte values (no repack); the broadcast pixel value is duplicated once.
// ---------------------------------------------------------------------------
template<int CIN, int COUT, int MT, bool LRELU>
__global__ __launch_bounds__(256, 2)
void conv3x3_kernel(const float* __restrict__ in,
                    const float* __restrict__ wt,
                    const float* __restrict__ bias,
                    float* __restrict__ out)
{
    constexpr int NT    = 128;
    constexpr int KC    = 8;
    constexpr int KSTEP = KC * 9;          // 72
    constexpr int MR    = MT / 8;          // 8 (MT=64) or 6 (MT=48)
    constexpr int MP    = MR / 2;          // channel pairs per thread
    constexpr int IPAD  = NT + 4;          // 132: 16B-aligned rows
    constexpr int WPAD  = (MT + 4) & ~3;   // 68 / 52 (16B-aligned rows)

    __shared__ __align__(16) float s_in[KC][3][IPAD];
    __shared__ __align__(16) float s_w[KSTEP][WPAD];

    const int tid = threadIdx.x;
    const int tx  = tid & 31;    // pixel group: pixels tx*4 .. tx*4+3
    const int ty  = tid >> 5;    // channel group: channels ty*MR .. +MR-1

    const int x0 = blockIdx.x * NT;
    const int y  = blockIdx.y;
    constexpr int MTILES = COUT / MT;
    const int n   = blockIdx.z / MTILES;
    const int co0 = (blockIdx.z % MTILES) * MT;

    ull acc[MP][4];
    #pragma unroll
    for (int p = 0; p < MP; p++)
        #pragma unroll
        for (int j = 0; j < 4; j++) acc[p][j] = 0ull;

    for (int ci0 = 0; ci0 < CIN; ci0 += KC) {
        __syncthreads();  // protect previous chunk's smem reads

        // --- stage input tile: KC channels x 3 rows x (NT+2) cols (halo) ---
        constexpr int IN_ELEMS = KC * 3 * (NT + 2);
        for (int idx = tid; idx < IN_ELEMS; idx += 256) {
            int ci  = idx / (3 * (NT + 2));
            int rem = idx % (3 * (NT + 2));
            int ky  = rem / (NT + 2);
            int xx  = rem % (NT + 2);
            int gy = y + ky - 1;
            int gx = x0 + xx - 1;
            float v = 0.0f;
            if ((unsigned)gy < (unsigned)cH && (unsigned)gx < (unsigned)cW)
                v = in[((n * CIN + ci0 + ci) * cH + gy) * cW + gx];
            s_in[ci][ky][xx] = v;
        }

        // --- stage weights k-major: s_w[k][co_l] (coalesced global reads) ---
        constexpr int W_ELEMS = MT * KSTEP;
        for (int idx = tid; idx < W_ELEMS; idx += 256) {
            int co_l = idx / KSTEP;
            int kk   = idx % KSTEP;
            s_w[kk][co_l] = wt[((co0 + co_l) * CIN + ci0) * 9 + kk];
        }
        __syncthreads();

        // --- compute: 72 k-steps; 6-wide sliding pixel window per (ci,ky) ---
        #pragma unroll
        for (int ci = 0; ci < KC; ci++) {
            #pragma unroll
            for (int ky = 0; ky < 3; ky++) {
                const float* bp = &s_in[ci][ky][tx * 4];
                float4 blo = *reinterpret_cast<const float4*>(bp);
                float2 bhi = *reinterpret_cast<const float2*>(bp + 4);
                ull bd[6];
                bd[0] = pk_dup(blo.x); bd[1] = pk_dup(blo.y);
                bd[2] = pk_dup(blo.z); bd[3] = pk_dup(blo.w);
                bd[4] = pk_dup(bhi.x); bd[5] = pk_dup(bhi.y);
                #pragma unroll
                for (int kx = 0; kx < 3; kx++) {
                    const int k = ci * 9 + ky * 3 + kx;
                    const ull* ap = reinterpret_cast<const ull*>(&s_w[k][ty * MR]);
                    #pragma unroll
                    for (int p = 0; p < MP; p++) {
                        const ull a = ap[p];   // weight pair (co, co+1)
                        #pragma unroll
                        for (int j = 0; j < 4; j++)
                            fma2(acc[p][j], a, bd[kx + j]);
                    }
                }
            }
        }
    }

    // --- epilogue: unpack channel pairs, bias (+ LeakyReLU), vector store ---
    #pragma unroll
    for (int p = 0; p < MP; p++) {
        float lo[4], hi[4];
        #pragma unroll
        for (int j = 0; j < 4; j++) unpk(lo[j], hi[j], acc[p][j]);

        #pragma unroll
        for (int half = 0; half < 2; half++) {
            const int co = co0 + ty * MR + 2 * p + half;
            const float bs = __ldg(&bias[co]);
            const float* v4 = half ? hi : lo;
            float4 v;
            v.x = v4[0] + bs; v.y = v4[1] + bs;
            v.z = v4[2] + bs; v.w = v4[3] + bs;
            if (LRELU) {
                v.x = v.x > 0.f ? v.x : 0.1f * v.x;
                v.y = v.y > 0.f ? v.y : 0.1f * v.y;
                v.z = v.z > 0.f ? v.z : 0.1f * v.z;
                v.w = v.w > 0.f ? v.w : 0.1f * v.w;
            }
            *reinterpret_cast<float4*>(
                &out[((n * COUT + co) * cH + y) * cW + x0 + tx * 4]) = v;
        }
    }
}

// ---------------------------------------------------------------------------
// Softmax over 9 kernel positions + convex combination + 4x pixel shuffle.
// One thread per (n, y, x). mask channel layout: k*16 + a*4 + b.
// ---------------------------------------------------------------------------
__global__ __launch_bounds__(256)
void upsample_kernel(const float* __restrict__ flow,
                     const float* __restrict__ mask,
                     float* __restrict__ out)
{
    const int idx = blockIdx.x * blockDim.x + threadIdx.x;
    if (idx >= cN * HW) return;
    const int x = idx % cW;
    const int y = (idx / cW) % cH;
    const int n = idx / HW;

    float fpx[9], fpy[9];
    #pragma unroll
    for (int ki = 0; ki < 3; ki++)
        #pragma unroll
        for (int kj = 0; kj < 3; kj++) {
            const int k = ki * 3 + kj;
            const int yy = y + ki - 1, xx = x + kj - 1;
            const bool ok = (unsigned)yy < (unsigned)cH && (unsigned)xx < (unsigned)cW;
            fpx[k] = ok ? 4.0f * flow[(n * 2 + 0) * HW + yy * cW + xx] : 0.0f;
            fpy[k] = ok ? 4.0f * flow[(n * 2 + 1) * HW + yy * cW + xx] : 0.0f;
        }

    const long base = (long)n * COUT2 * HW + y * cW + x;
    const int OH = 4 * cH, OW = 4 * cW;

    #pragma unroll
    for (int a = 0; a < 4; a++) {
        #pragma unroll
        for (int b = 0; b < 4; b++) {
            float m[9];
            float mx = -1e30f;
            #pragma unroll
            for (int k = 0; k < 9; k++) {
                m[k] = 0.25f * mask[base + (long)(k * 16 + a * 4 + b) * HW];
                mx = fmaxf(mx, m[k]);
            }
            float s = 0.0f;
            #pragma unroll
            for (int k = 0; k < 9; k++) { m[k] = __expf(m[k] - mx); s += m[k]; }
            const float inv = 1.0f / s;
            float ox = 0.0f, oy = 0.0f;
            #pragma unroll
            for (int k = 0; k < 9; k++) { ox += m[k] * fpx[k]; oy += m[k] * fpy[k]; }
            const int oyi = y * 4 + a, oxi = x * 4 + b;
            out[((n * 2 + 0) * OH + oyi) * OW + oxi] = ox * inv;
            out[((n * 2 + 1) * OH + oyi) * OW + oxi] = oy * inv;
        }
    }
}

// ---------------------------------------------------------------------------
extern "C" void kernel_launch(void* const* d_in, const int* in_sizes, int n_in,
                              void* d_out, int out_size)
{
    (void)in_sizes; (void)n_in; (void)out_size;
    const float* flow = (const float*)d_in[0];
    const float* feat = (const float*)d_in[1];
    const float* w1   = (const float*)d_in[2];
    const float* b1   = (const float*)d_in[3];
    const float* w2   = (const float*)d_in[4];
    const float* b2   = (const float*)d_in[5];
    float* out = (float*)d_out;

    float* hfeat; float* msk;
    cudaGetSymbolAddress((void**)&hfeat, g_hfeat);
    cudaGetSymbolAddress((void**)&msk, g_mask);

    // conv1: 96 -> 128, LeakyReLU(0.1). MT=64 -> 2 exact channel tiles, MR=8.
    {
        dim3 grid(cW / 128, cH, cN * (COUT1 / 64));
        conv3x3_kernel<CIN1, COUT1, 64, true><<<grid, 256>>>(feat, w1, b1, hfeat);
    }
    // conv2: 128 -> 144 (raw; 0.25 folded into softmax). MT=48 -> 3 tiles, MR=6.
    {
        dim3 grid(cW / 128, cH, cN * (COUT2 / 48));
        conv3x3_kernel<CIN2, COUT2, 48, false><<<grid, 256>>>(hfeat, w2, b2, msk);
    }
    // softmax + convex upsample + pixel shuffle
    {
        const int total = cN * HW;
        upsample_kernel<<<(total + 255) / 256, 256>>>(flow, msk, out);
    }
}

// round 3
// speedup vs baseline: 1.2337x; 1.0003x over previous
#include <cuda_runtime.h>
#include <math.h>

// Problem constants
constexpr int cN   = 4;
constexpr int cH   = 128;
constexpr int cW   = 256;
constexpr int CIN1 = 96,  COUT1 = 128;
constexpr int CIN2 = 128, COUT2 = 144;
constexpr int HW   = cH * cW;

// Scratch (static device allocation — no cudaMalloc allowed)
__device__ float g_hfeat[cN * COUT1 * cH * cW];
__device__ float g_mask [cN * COUT2 * cH * cW];

// ---- packed f32x2 helpers ----------------------------------------------
using ull = unsigned long long;

__device__ __forceinline__ ull pk_dup(float x) {
    ull r;
    asm("mov.b64 %0, {%1, %1};" : "=l"(r) : "f"(x));
    return r;
}
__device__ __forceinline__ void fma2(ull& d, ull a, ull b) {
    asm("fma.rn.f32x2 %0, %1, %2, %0;" : "+l"(d) : "l"(a), "l"(b));
}
__device__ __forceinline__ void unpk(float& lo, float& hi, ull v) {
    asm("mov.b64 {%0, %1}, %2;" : "=f"(lo), "=f"(hi) : "l"(v));
}

// ---------------------------------------------------------------------------
// 3x3 SAME conv, NCHW, register-blocked implicit GEMM with packed f32x2 FMA.
// Tile: NT=128 pixels (half a row) x MT output channels.
// 256 threads = 32 (pixel groups, 4 px each) x 8 (channel groups, MR ch each).
// Packing is over the CHANNEL dim: weight pairs load straight from smem as
// 8-byte values (no repack); the broadcast pixel value is duplicated once.
// ---------------------------------------------------------------------------
template<int CIN, int COUT, int MT, bool LRELU>
__global__ __launch_bounds__(256, 2)
void conv3x3_kernel(const float* __restrict__ in,
                    const float* __restrict__ wt,
                    const float* __restrict__ bias,
                    float* __restrict__ out)
{
    constexpr int NT    = 128;
    constexpr int KC    = 8;
    constexpr int KSTEP = KC * 9;          // 72
    constexpr int MR    = MT / 8;          // 8 (MT=64) or 6 (MT=48)
    constexpr int MP    = MR / 2;          // channel pairs per thread
    constexpr int IPAD  = NT + 4;          // 132: 16B-aligned rows
    constexpr int WPAD  = (MT + 4) & ~3;   // 68 / 52 (16B-aligned rows)

    __shared__ __align__(16) float s_in[KC][3][IPAD];
    __shared__ __align__(16) float s_w[KSTEP][WPAD];

    const int tid = threadIdx.x;
    const int tx  = tid & 31;    // pixel group: pixels tx*4 .. tx*4+3
    const int ty  = tid >> 5;    // channel group: channels ty*MR .. +MR-1

    const int x0 = blockIdx.x * NT;
    const int y  = blockIdx.y;
    constexpr int MTILES = COUT / MT;
    const int n   = blockIdx.z / MTILES;
    const int co0 = (blockIdx.z % MTILES) * MT;

    ull acc[MP][4];
    #pragma unroll
    for (int p = 0; p < MP; p++)
        #pragma unroll
        for (int j = 0; j < 4; j++) acc[p][j] = 0ull;

    for (int ci0 = 0; ci0 < CIN; ci0 += KC) {
        __syncthreads();  // protect previous chunk's smem reads

        // --- stage input tile: KC channels x 3 rows x (NT+2) cols (halo) ---
        constexpr int IN_ELEMS = KC * 3 * (NT + 2);
        for (int idx = tid; idx < IN_ELEMS; idx += 256) {
            int ci  = idx / (3 * (NT + 2));
            int rem = idx % (3 * (NT + 2));
            int ky  = rem / (NT + 2);
            int xx  = rem % (NT + 2);
            int gy = y + ky - 1;
            int gx = x0 + xx - 1;
            float v = 0.0f;
            if ((unsigned)gy < (unsigned)cH && (unsigned)gx < (unsigned)cW)
                v = in[((n * CIN + ci0 + ci) * cH + gy) * cW + gx];
            s_in[ci][ky][xx] = v;
        }

        // --- stage weights k-major: s_w[k][co_l] (coalesced global reads) ---
        constexpr int W_ELEMS = MT * KSTEP;
        for (int idx = tid; idx < W_ELEMS; idx += 256) {
            int co_l = idx / KSTEP;
            int kk   = idx % KSTEP;
            s_w[kk][co_l] = wt[((co0 + co_l) * CIN + ci0) * 9 + kk];
        }
        __syncthreads();

        // --- compute: 72 k-steps; 6-wide sliding pixel window per (ci,ky) ---
        #pragma unroll
        for (int ci = 0; ci < KC; ci++) {
            #pragma unroll
            for (int ky = 0; ky < 3; ky++) {
                const float* bp = &s_in[ci][ky][tx * 4];
                float4 blo = *reinterpret_cast<const float4*>(bp);
                float2 bhi = *reinterpret_cast<const float2*>(bp + 4);
                ull bd[6];
                bd[0] = pk_dup(blo.x); bd[1] = pk_dup(blo.y);
                bd[2] = pk_dup(blo.z); bd[3] = pk_dup(blo.w);
                bd[4] = pk_dup(bhi.x); bd[5] = pk_dup(bhi.y);
                #pragma unroll
                for (int kx = 0; kx < 3; kx++) {
                    const int k = ci * 9 + ky * 3 + kx;
                    const ull* ap = reinterpret_cast<const ull*>(&s_w[k][ty * MR]);
                    #pragma unroll
                    for (int p = 0; p < MP; p++) {
                        const ull a = ap[p];   // weight pair (co, co+1)
                        #pragma unroll
                        for (int j = 0; j < 4; j++)
                            fma2(acc[p][j], a, bd[kx + j]);
                    }
                }
            }
        }
    }

    // --- epilogue: unpack channel pairs, bias (+ LeakyReLU), vector store ---
    #pragma unroll
    for (int p = 0; p < MP; p++) {
        float lo[4], hi[4];
        #pragma unroll
        for (int j = 0; j < 4; j++) unpk(lo[j], hi[j], acc[p][j]);

        #pragma unroll
        for (int half = 0; half < 2; half++) {
            const int co = co0 + ty * MR + 2 * p + half;
            const float bs = __ldg(&bias[co]);
            const float* v4 = half ? hi : lo;
            float4 v;
            v.x = v4[0] + bs; v.y = v4[1] + bs;
            v.z = v4[2] + bs; v.w = v4[3] + bs;
            if (LRELU) {
                v.x = v.x > 0.f ? v.x : 0.1f * v.x;
                v.y = v.y > 0.f ? v.y : 0.1f * v.y;
                v.z = v.z > 0.f ? v.z : 0.1f * v.z;
                v.w = v.w > 0.f ? v.w : 0.1f * v.w;
            }
            *reinterpret_cast<float4*>(
                &out[((n * COUT + co) * cH + y) * cW + x0 + tx * 4]) = v;
        }
    }
}

// ---------------------------------------------------------------------------
// Softmax over 9 kernel positions + convex combination + 4x pixel shuffle.
// One thread per (n, y, x). mask channel layout: k*16 + a*4 + b.
// ---------------------------------------------------------------------------
__global__ __launch_bounds__(256)
void upsample_kernel(const float* __restrict__ flow,
                     const float* __restrict__ mask,
                     float* __restrict__ out)
{
    const int idx = blockIdx.x * blockDim.x + threadIdx.x;
    if (idx >= cN * HW) return;
    const int x = idx % cW;
    const int y = (idx / cW) % cH;
    const int n = idx / HW;

    float fpx[9], fpy[9];
    #pragma unroll
    for (int ki = 0; ki < 3; ki++)
        #pragma unroll
        for (int kj = 0; kj < 3; kj++) {
            const int k = ki * 3 + kj;
            const int yy = y + ki - 1, xx = x + kj - 1;
            const bool ok = (unsigned)yy < (unsigned)cH && (unsigned)xx < (unsigned)cW;
            fpx[k] = ok ? 4.0f * flow[(n * 2 + 0) * HW + yy * cW + xx] : 0.0f;
            fpy[k] = ok ? 4.0f * flow[(n * 2 + 1) * HW + yy * cW + xx] : 0.0f;
        }

    const long base = (long)n * COUT2 * HW + y * cW + x;
    const int OH = 4 * cH, OW = 4 * cW;

    #pragma unroll
    for (int a = 0; a < 4; a++) {
        #pragma unroll
        for (int b = 0; b < 4; b++) {
            float m[9];
            float mx = -1e30f;
            #pragma unroll
            for (int k = 0; k < 9; k++) {
                m[k] = 0.25f * mask[base + (long)(k * 16 + a * 4 + b) * HW];
                mx = fmaxf(mx, m[k]);
            }
            float s = 0.0f;
            #pragma unroll
            for (int k = 0; k < 9; k++) { m[k] = __expf(m[k] - mx); s += m[k]; }
            const float inv = 1.0f / s;
            float ox = 0.0f, oy = 0.0f;
            #pragma unroll
            for (int k = 0; k < 9; k++) { ox += m[k] * fpx[k]; oy += m[k] * fpy[k]; }
            const int oyi = y * 4 + a, oxi = x * 4 + b;
            out[((n * 2 + 0) * OH + oyi) * OW + oxi] = ox * inv;
            out[((n * 2 + 1) * OH + oyi) * OW + oxi] = oy * inv;
        }
    }
}

// ---------------------------------------------------------------------------
extern "C" void kernel_launch(void* const* d_in, const int* in_sizes, int n_in,
                              void* d_out, int out_size)
{
    (void)in_sizes; (void)n_in; (void)out_size;
    const float* flow = (const float*)d_in[0];
    const float* feat = (const float*)d_in[1];
    const float* w1   = (const float*)d_in[2];
    const float* b1   = (const float*)d_in[3];
    const float* w2   = (const float*)d_in[4];
    const float* b2   = (const float*)d_in[5];
    float* out = (float*)d_out;

    float* hfeat; float* msk;
    cudaGetSymbolAddress((void**)&hfeat, g_hfeat);
    cudaGetSymbolAddress((void**)&msk, g_mask);

    // conv1: 96 -> 128, LeakyReLU(0.1). MT=64 -> 2 exact channel tiles, MR=8.
    {
        dim3 grid(cW / 128, cH, cN * (COUT1 / 64));
        conv3x3_kernel<CIN1, COUT1, 64, true><<<grid, 256>>>(feat, w1, b1, hfeat);
    }
    // conv2: 128 -> 144 (raw; 0.25 folded into softmax). MT=48 -> 3 tiles, MR=6.
    {
        dim3 grid(cW / 128, cH, cN * (COUT2 / 48));
        conv3x3_kernel<CIN2, COUT2, 48, false><<<grid, 256>>>(hfeat, w2, b2, msk);
    }
    // softmax + convex upsample + pixel shuffle
    {
        const int total = cN * HW;
        upsample_kernel<<<(total + 255) / 256, 256>>>(flow, msk, out);
    }
}

// round 4
// speedup vs baseline: 1.3246x; 1.0737x over previous
#include <cuda_runtime.h>
#include <math.h>

// Problem constants
constexpr int cN   = 4;
constexpr int cH   = 128;
constexpr int cW   = 256;
constexpr int CIN1 = 96,  COUT1 = 128;
constexpr int CIN2 = 128, COUT2 = 144;
constexpr int HW   = cH * cW;

// Scratch (static device allocation — no cudaMalloc allowed)
__device__ float g_hfeat[cN * COUT1 * cH * cW];
__device__ float g_mask [cN * COUT2 * cH * cW];

// ---- packed f32x2 helpers ----------------------------------------------
using ull = unsigned long long;

__device__ __forceinline__ ull pk_dup(float x) {
    ull r;
    asm("mov.b64 %0, {%1, %1};" : "=l"(r) : "f"(x));
    return r;
}
__device__ __forceinline__ void fma2(ull& d, ull a, ull b) {
    asm("fma.rn.f32x2 %0, %1, %2, %0;" : "+l"(d) : "l"(a), "l"(b));
}
__device__ __forceinline__ void unpk(float& lo, float& hi, ull v) {
    asm("mov.b64 {%0, %1}, %2;" : "=f"(lo), "=f"(hi) : "l"(v));
}

// ---------------------------------------------------------------------------
// 3x3 SAME conv, NCHW, register-blocked implicit GEMM with packed f32x2 FMA.
// Tile: NT=128 pixels (half a row) x MT output channels.
// 256 threads = 32 (pixel groups, 4 px each) x 8 (channel groups, MR ch each).
// f32x2 packs over the CHANNEL dim: weight pairs come straight out of smem
// as 8-byte LDS.64 broadcasts; only the pixel broadcast needs a dup MOV.
// WPAD chosen so the weight-staging STS stride is 6 banks (2-way conflict
// max) while keeping rows 8B-aligned for the compute-side LDS.64.
// ---------------------------------------------------------------------------
template<int CIN, int COUT, int MT, bool LRELU>
__global__ __launch_bounds__(256, 3)
void conv3x3_kernel(const float* __restrict__ in,
                    const float* __restrict__ wt,
                    const float* __restrict__ bias,
                    float* __restrict__ out)
{
    constexpr int NT    = 128;
    constexpr int KC    = 8;
    constexpr int KSTEP = KC * 9;          // 72
    constexpr int MR    = MT / 8;          // 8 (MT=64) or 6 (MT=48)
    constexpr int MP    = MR / 2;          // channel pairs per thread
    constexpr int IPAD  = NT + 4;          // 132: 16B-aligned rows
    constexpr int WPAD  = MT + 6;          // 70 / 54: stride%32 = 6 -> 2-way

    __shared__ __align__(16) float s_in[KC][3][IPAD];
    __shared__ __align__(16) float s_w[KSTEP][WPAD];

    const int tid = threadIdx.x;
    const int tx  = tid & 31;    // pixel group: pixels tx*4 .. tx*4+3
    const int ty  = tid >> 5;    // channel group: channels ty*MR .. +MR-1

    const int x0 = blockIdx.x * NT;
    const int y  = blockIdx.y;
    constexpr int MTILES = COUT / MT;
    const int n   = blockIdx.z / MTILES;
    const int co0 = (blockIdx.z % MTILES) * MT;

    ull acc[MP][4];
    #pragma unroll
    for (int p = 0; p < MP; p++)
        #pragma unroll
        for (int j = 0; j < 4; j++) acc[p][j] = 0ull;

    for (int ci0 = 0; ci0 < CIN; ci0 += KC) {
        __syncthreads();  // protect previous chunk's smem reads

        // --- stage input tile: KC channels x 3 rows x (NT+2) cols (halo) ---
        constexpr int IN_ELEMS = KC * 3 * (NT + 2);
        #pragma unroll 4
        for (int idx = tid; idx < IN_ELEMS; idx += 256) {
            int ci  = idx / (3 * (NT + 2));
            int rem = idx % (3 * (NT + 2));
            int ky  = rem / (NT + 2);
            int xx  = rem % (NT + 2);
            int gy = y + ky - 1;
            int gx = x0 + xx - 1;
            float v = 0.0f;
            if ((unsigned)gy < (unsigned)cH && (unsigned)gx < (unsigned)cW)
                v = in[((n * CIN + ci0 + ci) * cH + gy) * cW + gx];
            s_in[ci][ky][xx] = v;
        }

        // --- stage weights k-major: s_w[k][co_l] (coalesced global reads) ---
        constexpr int W_ELEMS = MT * KSTEP;
        #pragma unroll 4
        for (int idx = tid; idx < W_ELEMS; idx += 256) {
            int co_l = idx / KSTEP;
            int kk   = idx % KSTEP;
            s_w[kk][co_l] = wt[((co0 + co_l) * CIN + ci0) * 9 + kk];
        }
        __syncthreads();

        // --- compute: 72 k-steps; 6-wide sliding pixel window per (ci,ky) ---
        #pragma unroll
        for (int ci = 0; ci < KC; ci++) {
            #pragma unroll
            for (int ky = 0; ky < 3; ky++) {
                const float* bp = &s_in[ci][ky][tx * 4];
                float4 blo = *reinterpret_cast<const float4*>(bp);
                float2 bhi = *reinterpret_cast<const float2*>(bp + 4);
                ull bd[6];
                bd[0] = pk_dup(blo.x); bd[1] = pk_dup(blo.y);
                bd[2] = pk_dup(blo.z); bd[3] = pk_dup(blo.w);
                bd[4] = pk_dup(bhi.x); bd[5] = pk_dup(bhi.y);
                #pragma unroll
                for (int kx = 0; kx < 3; kx++) {
                    const int k = ci * 9 + ky * 3 + kx;
                    const ull* ap = reinterpret_cast<const ull*>(&s_w[k][ty * MR]);
                    #pragma unroll
                    for (int p = 0; p < MP; p++) {
                        const ull a = ap[p];   // weight pair (co, co+1)
                        #pragma unroll
                        for (int j = 0; j < 4; j++)
                            fma2(acc[p][j], a, bd[kx + j]);
                    }
                }
            }
        }
    }

    // --- epilogue: unpack channel pairs, bias (+ LeakyReLU), vector store ---
    #pragma unroll
    for (int p = 0; p < MP; p++) {
        float lo[4], hi[4];
        #pragma unroll
        for (int j = 0; j < 4; j++) unpk(lo[j], hi[j], acc[p][j]);

        #pragma unroll
        for (int half = 0; half < 2; half++) {
            const int co = co0 + ty * MR + 2 * p + half;
            const float bs = __ldg(&bias[co]);
            const float* v4 = half ? hi : lo;
            float4 v;
            v.x = v4[0] + bs; v.y = v4[1] + bs;
            v.z = v4[2] + bs; v.w = v4[3] + bs;
            if (LRELU) {
                v.x = v.x > 0.f ? v.x : 0.1f * v.x;
                v.y = v.y > 0.f ? v.y : 0.1f * v.y;
                v.z = v.z > 0.f ? v.z : 0.1f * v.z;
                v.w = v.w > 0.f ? v.w : 0.1f * v.w;
            }
            *reinterpret_cast<float4*>(
                &out[((n * COUT + co) * cH + y) * cW + x0 + tx * 4]) = v;
        }
    }
}

// ---------------------------------------------------------------------------
// Softmax over 9 kernel positions + convex combination + 4x pixel shuffle.
// One thread per (n, y, x). mask channel layout: k*16 + a*4 + b.
// ---------------------------------------------------------------------------
__global__ __launch_bounds__(256)
void upsample_kernel(const float* __restrict__ flow,
                     const float* __restrict__ mask,
                     float* __restrict__ out)
{
    const int idx = blockIdx.x * blockDim.x + threadIdx.x;
    if (idx >= cN * HW) return;
    const int x = idx % cW;
    const int y = (idx / cW) % cH;
    const int n = idx / HW;

    float fpx[9], fpy[9];
    #pragma unroll
    for (int ki = 0; ki < 3; ki++)
        #pragma unroll
        for (int kj = 0; kj < 3; kj++) {
            const int k = ki * 3 + kj;
            const int yy = y + ki - 1, xx = x + kj - 1;
            const bool ok = (unsigned)yy < (unsigned)cH && (unsigned)xx < (unsigned)cW;
            fpx[k] = ok ? 4.0f * flow[(n * 2 + 0) * HW + yy * cW + xx] : 0.0f;
            fpy[k] = ok ? 4.0f * flow[(n * 2 + 1) * HW + yy * cW + xx] : 0.0f;
        }

    const long base = (long)n * COUT2 * HW + y * cW + x;
    const int OH = 4 * cH, OW = 4 * cW;

    #pragma unroll
    for (int a = 0; a < 4; a++) {
        #pragma unroll
        for (int b = 0; b < 4; b++) {
            float m[9];
            float mx = -1e30f;
            #pragma unroll
            for (int k = 0; k < 9; k++) {
                m[k] = 0.25f * mask[base + (long)(k * 16 + a * 4 + b) * HW];
                mx = fmaxf(mx, m[k]);
            }
            float s = 0.0f;
            #pragma unroll
            for (int k = 0; k < 9; k++) { m[k] = __expf(m[k] - mx); s += m[k]; }
            const float inv = 1.0f / s;
            float ox = 0.0f, oy = 0.0f;
            #pragma unroll
            for (int k = 0; k < 9; k++) { ox += m[k] * fpx[k]; oy += m[k] * fpy[k]; }
            const int oyi = y * 4 + a, oxi = x * 4 + b;
            out[((n * 2 + 0) * OH + oyi) * OW + oxi] = ox * inv;
            out[((n * 2 + 1) * OH + oyi) * OW + oxi] = oy * inv;
        }
    }
}

// ---------------------------------------------------------------------------
extern "C" void kernel_launch(void* const* d_in, const int* in_sizes, int n_in,
                              void* d_out, int out_size)
{
    (void)in_sizes; (void)n_in; (void)out_size;
    const float* flow = (const float*)d_in[0];
    const float* feat = (const float*)d_in[1];
    const float* w1   = (const float*)d_in[2];
    const float* b1   = (const float*)d_in[3];
    const float* w2   = (const float*)d_in[4];
    const float* b2   = (const float*)d_in[5];
    float* out = (float*)d_out;

    float* hfeat; float* msk;
    cudaGetSymbolAddress((void**)&hfeat, g_hfeat);
    cudaGetSymbolAddress((void**)&msk, g_mask);

    // conv1: 96 -> 128, LeakyReLU(0.1). MT=64 -> 2 exact channel tiles, MR=8.
    {
        dim3 grid(cW / 128, cH, cN * (COUT1 / 64));
        conv3x3_kernel<CIN1, COUT1, 64, true><<<grid, 256>>>(feat, w1, b1, hfeat);
    }
    // conv2: 128 -> 144 (raw; 0.25 folded into softmax). MT=48 -> 3 tiles, MR=6.
    {
        dim3 grid(cW / 128, cH, cN * (COUT2 / 48));
        conv3x3_kernel<CIN2, COUT2, 48, false><<<grid, 256>>>(hfeat, w2, b2, msk);
    }
    // softmax + convex upsample + pixel shuffle
    {
        const int total = cN * HW;
        upsample_kernel<<<(total + 255) / 256, 256>>>(flow, msk, out);
    }
}

// round 5
// speedup vs baseline: 1.3259x; 1.0010x over previous
#include <cuda_runtime.h>
#include <math.h>

// Problem constants
constexpr int cN   = 4;
constexpr int cH   = 128;
constexpr int cW   = 256;
constexpr int CIN1 = 96,  COUT1 = 128;
constexpr int CIN2 = 128, COUT2 = 144;
constexpr int HW   = cH * cW;

// Scratch (static device allocation — no cudaMalloc allowed)
__device__ float g_hfeat[cN * COUT1 * cH * cW];
__device__ float g_mask [cN * COUT2 * cH * cW];

// ---- packed f32x2 helpers ----------------------------------------------
using ull = unsigned long long;

__device__ __forceinline__ ull pk_dup(float x) {
    ull r;
    asm("mov.b64 %0, {%1, %1};" : "=l"(r) : "f"(x));
    return r;
}
__device__ __forceinline__ void fma2(ull& d, ull a, ull b) {
    asm("fma.rn.f32x2 %0, %1, %2, %0;" : "+l"(d) : "l"(a), "l"(b));
}
__device__ __forceinline__ void unpk(float& lo, float& hi, ull v) {
    asm("mov.b64 {%0, %1}, %2;" : "=f"(lo), "=f"(hi) : "l"(v));
}

// ---------------------------------------------------------------------------
// 3x3 SAME conv, NCHW, register-blocked implicit GEMM with packed f32x2 FMA.
// Tile: NT=128 pixels (half a row) x MT output channels.
// 256 threads = 32 (pixel groups, 4 px each) x 8 (channel groups, MR ch each).
// f32x2 packs over the CHANNEL dim: weight pairs come straight out of smem
// as 8-byte LDS.64 broadcasts; only the pixel broadcast needs a dup MOV.
// WPAD chosen so the weight-staging STS stride is 6 banks (2-way conflict
// max) while keeping rows 8B-aligned for the compute-side LDS.64.
// ---------------------------------------------------------------------------
template<int CIN, int COUT, int MT, bool LRELU>
__global__ __launch_bounds__(256, 3)
void conv3x3_kernel(const float* __restrict__ in,
                    const float* __restrict__ wt,
                    const float* __restrict__ bias,
                    float* __restrict__ out)
{
    constexpr int NT    = 128;
    constexpr int KC    = 8;
    constexpr int KSTEP = KC * 9;          // 72
    constexpr int MR    = MT / 8;          // 8 (MT=64) or 6 (MT=48)
    constexpr int MP    = MR / 2;          // channel pairs per thread
    constexpr int IPAD  = NT + 4;          // 132: 16B-aligned rows
    constexpr int WPAD  = MT + 6;          // 70 / 54: stride%32 = 6 -> 2-way

    __shared__ __align__(16) float s_in[KC][3][IPAD];
    __shared__ __align__(16) float s_w[KSTEP][WPAD];

    const int tid = threadIdx.x;
    const int tx  = tid & 31;    // pixel group: pixels tx*4 .. tx*4+3
    const int ty  = tid >> 5;    // channel group: channels ty*MR .. +MR-1

    const int x0 = blockIdx.x * NT;
    const int y  = blockIdx.y;
    constexpr int MTILES = COUT / MT;
    const int n   = blockIdx.z / MTILES;
    const int co0 = (blockIdx.z % MTILES) * MT;

    ull acc[MP][4];
    #pragma unroll
    for (int p = 0; p < MP; p++)
        #pragma unroll
        for (int j = 0; j < 4; j++) acc[p][j] = 0ull;

    for (int ci0 = 0; ci0 < CIN; ci0 += KC) {
        __syncthreads();  // protect previous chunk's smem reads

        // --- stage input tile: KC channels x 3 rows x (NT+2) cols (halo) ---
        constexpr int IN_ELEMS = KC * 3 * (NT + 2);
        #pragma unroll 4
        for (int idx = tid; idx < IN_ELEMS; idx += 256) {
            int ci  = idx / (3 * (NT + 2));
            int rem = idx % (3 * (NT + 2));
            int ky  = rem / (NT + 2);
            int xx  = rem % (NT + 2);
            int gy = y + ky - 1;
            int gx = x0 + xx - 1;
            float v = 0.0f;
            if ((unsigned)gy < (unsigned)cH && (unsigned)gx < (unsigned)cW)
                v = in[((n * CIN + ci0 + ci) * cH + gy) * cW + gx];
            s_in[ci][ky][xx] = v;
        }

        // --- stage weights k-major: s_w[k][co_l] (coalesced global reads) ---
        constexpr int W_ELEMS = MT * KSTEP;
        #pragma unroll 4
        for (int idx = tid; idx < W_ELEMS; idx += 256) {
            int co_l = idx / KSTEP;
            int kk   = idx % KSTEP;
            s_w[kk][co_l] = wt[((co0 + co_l) * CIN + ci0) * 9 + kk];
        }
        __syncthreads();

        // --- compute: 72 k-steps; 6-wide sliding pixel window per (ci,ky) ---
        #pragma unroll
        for (int ci = 0; ci < KC; ci++) {
            #pragma unroll
            for (int ky = 0; ky < 3; ky++) {
                const float* bp = &s_in[ci][ky][tx * 4];
                float4 blo = *reinterpret_cast<const float4*>(bp);
                float2 bhi = *reinterpret_cast<const float2*>(bp + 4);
                ull bd[6];
                bd[0] = pk_dup(blo.x); bd[1] = pk_dup(blo.y);
                bd[2] = pk_dup(blo.z); bd[3] = pk_dup(blo.w);
                bd[4] = pk_dup(bhi.x); bd[5] = pk_dup(bhi.y);
                #pragma unroll
                for (int kx = 0; kx < 3; kx++) {
                    const int k = ci * 9 + ky * 3 + kx;
                    const ull* ap = reinterpret_cast<const ull*>(&s_w[k][ty * MR]);
                    #pragma unroll
                    for (int p = 0; p < MP; p++) {
                        const ull a = ap[p];   // weight pair (co, co+1)
                        #pragma unroll
                        for (int j = 0; j < 4; j++)
                            fma2(acc[p][j], a, bd[kx + j]);
                    }
                }
            }
        }
    }

    // --- epilogue: unpack channel pairs, bias (+ LeakyReLU), vector store ---
    #pragma unroll
    for (int p = 0; p < MP; p++) {
        float lo[4], hi[4];
        #pragma unroll
        for (int j = 0; j < 4; j++) unpk(lo[j], hi[j], acc[p][j]);

        #pragma unroll
        for (int half = 0; half < 2; half++) {
            const int co = co0 + ty * MR + 2 * p + half;
            const float bs = __ldg(&bias[co]);
            const float* v4 = half ? hi : lo;
            float4 v;
            v.x = v4[0] + bs; v.y = v4[1] + bs;
            v.z = v4[2] + bs; v.w = v4[3] + bs;
            if (LRELU) {
                v.x = v.x > 0.f ? v.x : 0.1f * v.x;
                v.y = v.y > 0.f ? v.y : 0.1f * v.y;
                v.z = v.z > 0.f ? v.z : 0.1f * v.z;
                v.w = v.w > 0.f ? v.w : 0.1f * v.w;
            }
            *reinterpret_cast<float4*>(
                &out[((n * COUT + co) * cH + y) * cW + x0 + tx * 4]) = v;
        }
    }
}

// ---------------------------------------------------------------------------
// Softmax over 9 kernel positions + convex combination + 4x pixel shuffle.
// One thread per (n, y, x). mask channel layout: k*16 + a*4 + b.
// ---------------------------------------------------------------------------
__global__ __launch_bounds__(256)
void upsample_kernel(const float* __restrict__ flow,
                     const float* __restrict__ mask,
                     float* __restrict__ out)
{
    const int idx = blockIdx.x * blockDim.x + threadIdx.x;
    if (idx >= cN * HW) return;
    const int x = idx % cW;
    const int y = (idx / cW) % cH;
    const int n = idx / HW;

    float fpx[9], fpy[9];
    #pragma unroll
    for (int ki = 0; ki < 3; ki++)
        #pragma unroll
        for (int kj = 0; kj < 3; kj++) {
            const int k = ki * 3 + kj;
            const int yy = y + ki - 1, xx = x + kj - 1;
            const bool ok = (unsigned)yy < (unsigned)cH && (unsigned)xx < (unsigned)cW;
            fpx[k] = ok ? 4.0f * flow[(n * 2 + 0) * HW + yy * cW + xx] : 0.0f;
            fpy[k] = ok ? 4.0f * flow[(n * 2 + 1) * HW + yy * cW + xx] : 0.0f;
        }

    const long base = (long)n * COUT2 * HW + y * cW + x;
    const int OH = 4 * cH, OW = 4 * cW;

    #pragma unroll
    for (int a = 0; a < 4; a++) {
        #pragma unroll
        for (int b = 0; b < 4; b++) {
            float m[9];
            float mx = -1e30f;
            #pragma unroll
            for (int k = 0; k < 9; k++) {
                m[k] = 0.25f * mask[base + (long)(k * 16 + a * 4 + b) * HW];
                mx = fmaxf(mx, m[k]);
            }
            float s = 0.0f;
            #pragma unroll
            for (int k = 0; k < 9; k++) { m[k] = __expf(m[k] - mx); s += m[k]; }
            const float inv = 1.0f / s;
            float ox = 0.0f, oy = 0.0f;
            #pragma unroll
            for (int k = 0; k < 9; k++) { ox += m[k] * fpx[k]; oy += m[k] * fpy[k]; }
            const int oyi = y * 4 + a, oxi = x * 4 + b;
            out[((n * 2 + 0) * OH + oyi) * OW + oxi] = ox * inv;
            out[((n * 2 + 1) * OH + oyi) * OW + oxi] = oy * inv;
        }
    }
}

// ---------------------------------------------------------------------------
extern "C" void kernel_launch(void* const* d_in, const int* in_sizes, int n_in,
                              void* d_out, int out_size)
{
    (void)in_sizes; (void)n_in; (void)out_size;
    const float* flow = (const float*)d_in[0];
    const float* feat = (const float*)d_in[1];
    const float* w1   = (const float*)d_in[2];
    const float* b1   = (const float*)d_in[3];
    const float* w2   = (const float*)d_in[4];
    const float* b2   = (const float*)d_in[5];
    float* out = (float*)d_out;

    float* hfeat; float* msk;
    cudaGetSymbolAddress((void**)&hfeat, g_hfeat);
    cudaGetSymbolAddress((void**)&msk, g_mask);

    // conv1: 96 -> 128, LeakyReLU(0.1). MT=64 -> 2 exact channel tiles, MR=8.
    {
        dim3 grid(cW / 128, cH, cN * (COUT1 / 64));
        conv3x3_kernel<CIN1, COUT1, 64, true><<<grid, 256>>>(feat, w1, b1, hfeat);
    }
    // conv2: 128 -> 144 (raw; 0.25 folded into softmax). MT=48 -> 3 tiles, MR=6.
    {
        dim3 grid(cW / 128, cH, cN * (COUT2 / 48));
        conv3x3_kernel<CIN2, COUT2, 48, false><<<grid, 256>>>(hfeat, w2, b2, msk);
    }
    // softmax + convex upsample + pixel shuffle
    {
        const int total = cN * HW;
        upsample_kernel<<<(total + 255) / 256, 256>>>(flow, msk, out);
    }
}